// round 1
// baseline (speedup 1.0000x reference)
#include <cuda_runtime.h>

#define HH 512
#define WW 512
#define NB 16
#define HW (HH * WW)
#define NPIX (NB * HW)

#define EPS 0.0078125f               // 2^-7
#define SCALE (512.0f / 511.0f)      // H/(H-1)

// Ping-pong scratch (allocation-free per harness rules)
static __device__ float g_dispA[NB * 2 * HW];
static __device__ float g_dispB[NB * 2 * HW];
static __device__ float g_ldA[NB * HW];
static __device__ float g_ldB[NB * HW];

// ---------------------------------------------------------------------------
// Bilinear sampling with zero padding (matches torch grid_sample zeros /
// reference gather with per-corner validity).
// ---------------------------------------------------------------------------
__device__ __forceinline__ float tap(const float* __restrict__ s, int y, int x) {
    return ((unsigned)x < (unsigned)WW && (unsigned)y < (unsigned)HH)
               ? __ldg(s + y * WW + x) : 0.0f;
}

__device__ __forceinline__ float bilin1(const float* __restrict__ s, float sx, float sy) {
    float xf = floorf(sx), yf = floorf(sy);
    float wx = sx - xf, wy = sy - yf;
    int x0 = (int)xf, y0 = (int)yf;
    float v00, v01, v10, v11;
    if ((unsigned)x0 < (unsigned)(WW - 1) && (unsigned)y0 < (unsigned)(HH - 1)) {
        const float* r = s + y0 * WW + x0;
        v00 = __ldg(r); v01 = __ldg(r + 1); v10 = __ldg(r + WW); v11 = __ldg(r + WW + 1);
    } else {
        v00 = tap(s, y0, x0);     v01 = tap(s, y0, x0 + 1);
        v10 = tap(s, y0 + 1, x0); v11 = tap(s, y0 + 1, x0 + 1);
    }
    float a = v00 + wx * (v01 - v00);
    float b = v10 + wx * (v11 - v10);
    return a + wy * (b - a);
}

__device__ __forceinline__ float2 bilin2(const float* __restrict__ s0,
                                         const float* __restrict__ s1,
                                         float sx, float sy) {
    float xf = floorf(sx), yf = floorf(sy);
    float wx = sx - xf, wy = sy - yf;
    int x0 = (int)xf, y0 = (int)yf;
    float a00, a01, a10, a11, b00, b01, b10, b11;
    if ((unsigned)x0 < (unsigned)(WW - 1) && (unsigned)y0 < (unsigned)(HH - 1)) {
        int off = y0 * WW + x0;
        const float* r0 = s0 + off;
        const float* r1 = s1 + off;
        a00 = __ldg(r0); a01 = __ldg(r0 + 1); a10 = __ldg(r0 + WW); a11 = __ldg(r0 + WW + 1);
        b00 = __ldg(r1); b01 = __ldg(r1 + 1); b10 = __ldg(r1 + WW); b11 = __ldg(r1 + WW + 1);
    } else {
        a00 = tap(s0, y0, x0);     a01 = tap(s0, y0, x0 + 1);
        a10 = tap(s0, y0 + 1, x0); a11 = tap(s0, y0 + 1, x0 + 1);
        b00 = tap(s1, y0, x0);     b01 = tap(s1, y0, x0 + 1);
        b10 = tap(s1, y0 + 1, x0); b11 = tap(s1, y0 + 1, x0 + 1);
    }
    float pa = a00 + wx * (a01 - a00);
    float pb = a10 + wx * (a11 - a10);
    float qa = b00 + wx * (b01 - b00);
    float qb = b10 + wx * (b11 - b10);
    return make_float2(pa + wy * (pb - pa), qa + wy * (qb - qa));
}

// ---------------------------------------------------------------------------
// Init: disp0 = eps*vel ; ldjac0 = -sum_n (-eps)^n tr(J^n)/n  via Newton ids.
// Sobel Jacobian with replicate padding, cross-correlation semantics.
// ---------------------------------------------------------------------------
__global__ __launch_bounds__(256) void init_kernel(const float* __restrict__ vel,
                                                   float* __restrict__ disp,
                                                   float* __restrict__ ld) {
    int idx = blockIdx.x * blockDim.x + threadIdx.x;
    if (idx >= NPIX) return;
    int n = idx / HW;
    int p = idx - n * HW;
    int y = p / WW;
    int x = p - y * WW;

    const float* v0 = vel + (size_t)n * 2 * HW;   // vel_y channel
    const float* v1 = v0 + HW;                    // vel_x channel

    // disp0
    disp[(size_t)n * 2 * HW + p]      = EPS * __ldg(v0 + p);
    disp[(size_t)n * 2 * HW + HW + p] = EPS * __ldg(v1 + p);

    int ym = max(y - 1, 0), yp = min(y + 1, HH - 1);
    int xm = max(x - 1, 0), xp = min(x + 1, WW - 1);
    int rm = ym * WW, rc = y * WW, rp = yp * WW;

    float a00 = __ldg(v0 + rm + xm), a01 = __ldg(v0 + rm + x), a02 = __ldg(v0 + rm + xp);
    float a10 = __ldg(v0 + rc + xm),                           a12 = __ldg(v0 + rc + xp);
    float a20 = __ldg(v0 + rp + xm), a21 = __ldg(v0 + rp + x), a22 = __ldg(v0 + rp + xp);

    float c00 = __ldg(v1 + rm + xm), c01 = __ldg(v1 + rm + x), c02 = __ldg(v1 + rm + xp);
    float c10 = __ldg(v1 + rc + xm),                           c12 = __ldg(v1 + rc + xp);
    float c20 = __ldg(v1 + rp + xm), c21 = __ldg(v1 + rp + x), c22 = __ldg(v1 + rp + xp);

    // J00 = d(vel_y)/dy, J01 = d(vel_y)/dx, J10 = d(vel_x)/dy, J11 = d(vel_x)/dx
    float J00 = 0.125f * ((a20 + 2.0f * a21 + a22) - (a00 + 2.0f * a01 + a02));
    float J01 = 0.125f * ((a02 + 2.0f * a12 + a22) - (a00 + 2.0f * a10 + a20));
    float J10 = 0.125f * ((c20 + 2.0f * c21 + c22) - (c00 + 2.0f * c01 + c02));
    float J11 = 0.125f * ((c02 + 2.0f * c12 + c22) - (c00 + 2.0f * c10 + c20));

    float t = J00 + J11;
    float s = J00 * J11 - J01 * J10;
    float p1 = t;
    float p2 = t * t - 2.0f * s;
    float p3 = t * (t * t - 3.0f * s);
    float p4 = t * t * (t * t - 4.0f * s) + 2.0f * s * s;

    const float e1 = EPS;
    const float e2 = EPS * EPS;
    const float e3 = e2 * EPS;
    const float e4 = e2 * e2;
    float ldv = e1 * p1 - 0.5f * e2 * p2 + (e3 / 3.0f) * p3 - 0.25f * e4 * p4;
    ld[(size_t)n * HW + p] = ldv;
}

// ---------------------------------------------------------------------------
// One squaring step (fused disp + ldjac update; reads old, writes new).
// ---------------------------------------------------------------------------
__global__ __launch_bounds__(256) void step_kernel(const float* __restrict__ dispIn,
                                                   const float* __restrict__ ldIn,
                                                   float* __restrict__ dispOut,
                                                   float* __restrict__ ldOut) {
    int idx = blockIdx.x * blockDim.x + threadIdx.x;
    if (idx >= NPIX) return;
    int n = idx / HW;
    int p = idx - n * HW;
    int y = p / WW;
    int x = p - y * WW;

    const float* d0 = dispIn + (size_t)n * 2 * HW;  // dy plane
    const float* d1 = d0 + HW;                      // dx plane

    float dy0 = __ldg(d0 + p);
    float dx0 = __ldg(d1 + p);

    // sample disp at its own warped location
    float sy = ((float)y + dy0) * SCALE - 0.5f;
    float sx = ((float)x + dx0) * SCALE - 0.5f;
    float2 smp = bilin2(d0, d1, sx, sy);

    float ndy = dy0 + smp.x;
    float ndx = dx0 + smp.y;
    dispOut[(size_t)n * 2 * HW + p]      = ndy;
    dispOut[(size_t)n * 2 * HW + HW + p] = ndx;

    // ldjac warped by the NEW displacement
    const float* l = ldIn + (size_t)n * HW;
    float sy2 = ((float)y + ndy) * SCALE - 0.5f;
    float sx2 = ((float)x + ndx) * SCALE - 0.5f;
    float ls = bilin1(l, sx2, sy2);
    ldOut[(size_t)n * HW + p] = __ldg(l + p) + ls;
}

// ---------------------------------------------------------------------------
extern "C" void kernel_launch(void* const* d_in, const int* in_sizes, int n_in,
                              void* d_out, int out_size) {
    const float* vel = (const float*)d_in[0];
    float* out_disp = (float*)d_out;
    float* out_ld   = (float*)d_out + (size_t)NB * 2 * HW;

    float *dA, *dB, *lA, *lB;
    cudaGetSymbolAddress((void**)&dA, g_dispA);
    cudaGetSymbolAddress((void**)&dB, g_dispB);
    cudaGetSymbolAddress((void**)&lA, g_ldA);
    cudaGetSymbolAddress((void**)&lB, g_ldB);

    const int threads = 256;
    const int blocks = (NPIX + threads - 1) / threads;

    init_kernel<<<blocks, threads>>>(vel, dA, lA);
    // 7 squaring steps, ping-pong; final writes straight into d_out
    step_kernel<<<blocks, threads>>>(dA, lA, dB, lB);      // 1
    step_kernel<<<blocks, threads>>>(dB, lB, dA, lA);      // 2
    step_kernel<<<blocks, threads>>>(dA, lA, dB, lB);      // 3
    step_kernel<<<blocks, threads>>>(dB, lB, dA, lA);      // 4
    step_kernel<<<blocks, threads>>>(dA, lA, dB, lB);      // 5
    step_kernel<<<blocks, threads>>>(dB, lB, dA, lA);      // 6
    step_kernel<<<blocks, threads>>>(dA, lA, out_disp, out_ld);  // 7
}

// round 2
// speedup vs baseline: 1.2967x; 1.2967x over previous
#include <cuda_runtime.h>

#define HH 512
#define WW 512
#define NB 16
#define HW (HH * WW)
#define NPIX (NB * HW)

#define EPS 0.0078125f               // 2^-7
#define SCALE (512.0f / 511.0f)      // H/(H-1)

// Scratch: disp stored interleaved (float2 per pixel), ld scalar.
static __device__ float2 g_dispA[NB * HW];
static __device__ float2 g_dispB[NB * HW];
static __device__ float  g_ldA[NB * HW];
static __device__ float  g_ldB[NB * HW];

// ---------------------------------------------------------------------------
// Zero-padded taps
// ---------------------------------------------------------------------------
__device__ __forceinline__ float tap1(const float* __restrict__ s, int y, int x) {
    return ((unsigned)x < (unsigned)WW && (unsigned)y < (unsigned)HH)
               ? __ldg(s + y * WW + x) : 0.0f;
}
__device__ __forceinline__ float2 tap2(const float2* __restrict__ s, int y, int x) {
    return ((unsigned)x < (unsigned)WW && (unsigned)y < (unsigned)HH)
               ? __ldg(s + y * WW + x) : make_float2(0.0f, 0.0f);
}

__device__ __forceinline__ float bilin1(const float* __restrict__ s, float sx, float sy) {
    float xf = floorf(sx), yf = floorf(sy);
    float wx = sx - xf, wy = sy - yf;
    int x0 = (int)xf, y0 = (int)yf;
    float v00, v01, v10, v11;
    if ((unsigned)x0 < (unsigned)(WW - 1) && (unsigned)y0 < (unsigned)(HH - 1)) {
        const float* r = s + y0 * WW + x0;
        v00 = __ldg(r); v01 = __ldg(r + 1); v10 = __ldg(r + WW); v11 = __ldg(r + WW + 1);
    } else {
        v00 = tap1(s, y0, x0);     v01 = tap1(s, y0, x0 + 1);
        v10 = tap1(s, y0 + 1, x0); v11 = tap1(s, y0 + 1, x0 + 1);
    }
    float a = v00 + wx * (v01 - v00);
    float b = v10 + wx * (v11 - v10);
    return a + wy * (b - a);
}

// Bilinear on interleaved float2 field
__device__ __forceinline__ float2 bilin2i(const float2* __restrict__ s, float sx, float sy) {
    float xf = floorf(sx), yf = floorf(sy);
    float wx = sx - xf, wy = sy - yf;
    int x0 = (int)xf, y0 = (int)yf;
    float2 v00, v01, v10, v11;
    if ((unsigned)x0 < (unsigned)(WW - 1) && (unsigned)y0 < (unsigned)(HH - 1)) {
        const float2* r = s + y0 * WW + x0;
        v00 = __ldg(r); v01 = __ldg(r + 1); v10 = __ldg(r + WW); v11 = __ldg(r + WW + 1);
    } else {
        v00 = tap2(s, y0, x0);     v01 = tap2(s, y0, x0 + 1);
        v10 = tap2(s, y0 + 1, x0); v11 = tap2(s, y0 + 1, x0 + 1);
    }
    float ax = v00.x + wx * (v01.x - v00.x);
    float bx = v10.x + wx * (v11.x - v10.x);
    float ay = v00.y + wx * (v01.y - v00.y);
    float by = v10.y + wx * (v11.y - v10.y);
    return make_float2(ax + wy * (bx - ax), ay + wy * (by - ay));
}

// ---------------------------------------------------------------------------
// Init: disp0 = eps*vel (interleaved) ; ldjac0 via Newton identities on
// the 2x2 Sobel Jacobian (tr(J^n) from t=tr, s=det).
// ---------------------------------------------------------------------------
__global__ __launch_bounds__(256) void init_kernel(const float* __restrict__ vel,
                                                   float2* __restrict__ disp,
                                                   float* __restrict__ ld) {
    int idx = blockIdx.x * blockDim.x + threadIdx.x;
    if (idx >= NPIX) return;
    int n = idx >> 18;            // / HW (2^18)
    int p = idx & (HW - 1);
    int y = p >> 9;               // / WW
    int x = p & (WW - 1);

    const float* v0 = vel + (size_t)n * 2 * HW;   // vel_y plane
    const float* v1 = v0 + HW;                    // vel_x plane

    disp[(size_t)n * HW + p] = make_float2(EPS * __ldg(v0 + p), EPS * __ldg(v1 + p));

    int ym = max(y - 1, 0), yp = min(y + 1, HH - 1);
    int xm = max(x - 1, 0), xp = min(x + 1, WW - 1);
    int rm = ym * WW, rc = y * WW, rp = yp * WW;

    float a00 = __ldg(v0 + rm + xm), a01 = __ldg(v0 + rm + x), a02 = __ldg(v0 + rm + xp);
    float a10 = __ldg(v0 + rc + xm),                           a12 = __ldg(v0 + rc + xp);
    float a20 = __ldg(v0 + rp + xm), a21 = __ldg(v0 + rp + x), a22 = __ldg(v0 + rp + xp);

    float c00 = __ldg(v1 + rm + xm), c01 = __ldg(v1 + rm + x), c02 = __ldg(v1 + rm + xp);
    float c10 = __ldg(v1 + rc + xm),                           c12 = __ldg(v1 + rc + xp);
    float c20 = __ldg(v1 + rp + xm), c21 = __ldg(v1 + rp + x), c22 = __ldg(v1 + rp + xp);

    float J00 = 0.125f * ((a20 + 2.0f * a21 + a22) - (a00 + 2.0f * a01 + a02));
    float J01 = 0.125f * ((a02 + 2.0f * a12 + a22) - (a00 + 2.0f * a10 + a20));
    float J10 = 0.125f * ((c20 + 2.0f * c21 + c22) - (c00 + 2.0f * c01 + c02));
    float J11 = 0.125f * ((c02 + 2.0f * c12 + c22) - (c00 + 2.0f * c10 + c20));

    float t = J00 + J11;
    float s = J00 * J11 - J01 * J10;
    float p1 = t;
    float p2 = t * t - 2.0f * s;
    float p3 = t * (t * t - 3.0f * s);
    float p4 = t * t * (t * t - 4.0f * s) + 2.0f * s * s;

    const float e2 = EPS * EPS, e3 = e2 * EPS, e4 = e2 * e2;
    ld[(size_t)n * HW + p] = EPS * p1 - 0.5f * e2 * p2 + (e3 / 3.0f) * p3 - 0.25f * e4 * p4;
}

// ---------------------------------------------------------------------------
// One squaring step, 2 pixels per thread. FINAL=true writes planar to d_out.
// ---------------------------------------------------------------------------
template <bool FINAL>
__global__ __launch_bounds__(256) void step_kernel(const float2* __restrict__ dispIn,
                                                   const float*  __restrict__ ldIn,
                                                   float2* __restrict__ dispOut,   // !FINAL
                                                   float*  __restrict__ ldOut,     // !FINAL
                                                   float*  __restrict__ outBuf) {  // FINAL
    int idx = blockIdx.x * blockDim.x + threadIdx.x;   // NPIX/2 threads
    if (idx >= NPIX / 2) return;
    int n  = idx >> 17;                 // / (HW/2)
    int p2 = idx & (HW / 2 - 1);
    int y  = p2 >> 8;                   // / (WW/2)
    int x  = (p2 & 255) << 1;           // even x
    int p  = y * WW + x;

    const float2* d = dispIn + (size_t)n * HW;
    const float*  l = ldIn   + (size_t)n * HW;

    // center disp for the pixel pair: one 16B load
    float4 c = __ldg(reinterpret_cast<const float4*>(d + p));
    float dy0 = c.x, dx0 = c.y, dy1 = c.z, dx1 = c.w;

    float fy = (float)y;

    // --- pixel 0 ---
    float sy0 = (fy + dy0) * SCALE - 0.5f;
    float sx0 = ((float)x + dx0) * SCALE - 0.5f;
    float2 s0 = bilin2i(d, sx0, sy0);
    float ndy0 = dy0 + s0.x, ndx0 = dx0 + s0.y;

    // --- pixel 1 ---
    float sy1 = (fy + dy1) * SCALE - 0.5f;
    float sx1 = ((float)(x + 1) + dx1) * SCALE - 0.5f;
    float2 s1 = bilin2i(d, sx1, sy1);
    float ndy1 = dy1 + s1.x, ndx1 = dx1 + s1.y;

    // --- ldjac: warp by NEW displacement ---
    float2 lc = __ldg(reinterpret_cast<const float2*>(l + p));
    float ls0 = bilin1(l, ((float)x + ndx0) * SCALE - 0.5f, (fy + ndy0) * SCALE - 0.5f);
    float ls1 = bilin1(l, ((float)(x + 1) + ndx1) * SCALE - 0.5f, (fy + ndy1) * SCALE - 0.5f);
    float nl0 = lc.x + ls0, nl1 = lc.y + ls1;

    if (FINAL) {
        // planar output: [N,2,H,W] disp then [N,1,H,W] ldjac
        float* od = outBuf + (size_t)n * 2 * HW;
        *reinterpret_cast<float2*>(od + p)      = make_float2(ndy0, ndy1);
        *reinterpret_cast<float2*>(od + HW + p) = make_float2(ndx0, ndx1);
        float* ol = outBuf + (size_t)NB * 2 * HW + (size_t)n * HW;
        *reinterpret_cast<float2*>(ol + p) = make_float2(nl0, nl1);
    } else {
        *reinterpret_cast<float4*>(dispOut + (size_t)n * HW + p) =
            make_float4(ndy0, ndx0, ndy1, ndx1);
        *reinterpret_cast<float2*>(ldOut + (size_t)n * HW + p) = make_float2(nl0, nl1);
    }
}

// ---------------------------------------------------------------------------
extern "C" void kernel_launch(void* const* d_in, const int* in_sizes, int n_in,
                              void* d_out, int out_size) {
    const float* vel = (const float*)d_in[0];
    float* out = (float*)d_out;

    float2 *dA, *dB;
    float *lA, *lB;
    cudaGetSymbolAddress((void**)&dA, g_dispA);
    cudaGetSymbolAddress((void**)&dB, g_dispB);
    cudaGetSymbolAddress((void**)&lA, g_ldA);
    cudaGetSymbolAddress((void**)&lB, g_ldB);

    const int threads = 256;
    const int blocksInit = (NPIX + threads - 1) / threads;
    const int blocksStep = (NPIX / 2 + threads - 1) / threads;

    init_kernel<<<blocksInit, threads>>>(vel, dA, lA);
    step_kernel<false><<<blocksStep, threads>>>(dA, lA, dB, lB, nullptr);  // 1
    step_kernel<false><<<blocksStep, threads>>>(dB, lB, dA, lA, nullptr);  // 2
    step_kernel<false><<<blocksStep, threads>>>(dA, lA, dB, lB, nullptr);  // 3
    step_kernel<false><<<blocksStep, threads>>>(dB, lB, dA, lA, nullptr);  // 4
    step_kernel<false><<<blocksStep, threads>>>(dA, lA, dB, lB, nullptr);  // 5
    step_kernel<false><<<blocksStep, threads>>>(dB, lB, dA, lA, nullptr);  // 6
    step_kernel<true><<<blocksStep, threads>>>(dA, lA, nullptr, nullptr, out);  // 7
}